// round 16
// baseline (speedup 1.0000x reference)
#include <cuda_runtime.h>
#include <cuda_fp16.h>
#include <cstdint>
#include <math.h>

// ===========================================================================
// TaskGraphGAT — round 14: R14 kernel + CTA phase-stagger. Co-resident CTAs
// (2/SM) were phase-locked (tensor 32% = correlated bound). Delay the wave-1
// second-slot CTAs by ~half a head period so each SMSP's two warps (one per
// CTA) run GEMM phases against the other's scalar phases. Offset self-
// perpetuates across waves; one-time cost <1%.
// ===========================================================================

#define PB 272          // fp16 tile pitch in BYTES (136 halves)

// ---------------- SMEM map (bytes) ----------------
#define SM_HHI   0          // h hi (64 x 136 fp16 = 17408 B) -> GEMM1 A
#define SM_HLO   17408      // h lo (residual accuracy only)
#define SM_W     34816      // W tile fp16, 136 rows x PB = 36992 B (rows 128/129 = wa)
#define SM_OW    71808      // outW tile fp16, 128 rows x PB = 34816 B
#define SM_SMALL 106624     // lnb[768] | ewf[64] | adji[64]
#define SMEM_BYTES 110208

// ---------------- device globals (written by prep) ----------------
__device__ float g_htask[8 * 128];
__device__ __align__(16) __half g_W[8 * 18496];    // pre-pitched 136x136 tiles
__device__ __align__(16) __half g_OW[8 * 16384];   // out_W rearranged fp16

// ---------------- helpers ----------------
__device__ __forceinline__ uint32_t smem_u32(const void* p) {
    uint32_t a;
    asm("{ .reg .u64 t; cvta.to.shared.u64 t, %1; cvt.u32.u64 %0, t; }" : "=r"(a) : "l"(p));
    return a;
}
__device__ __forceinline__ void ldsm4(uint32_t* r, uint32_t a) {
    asm volatile("ldmatrix.sync.aligned.m8n8.x4.shared.b16 {%0,%1,%2,%3}, [%4];"
                 : "=r"(r[0]), "=r"(r[1]), "=r"(r[2]), "=r"(r[3]) : "r"(a));
}
__device__ __forceinline__ void ldsm2(uint32_t* r, uint32_t a) {
    asm volatile("ldmatrix.sync.aligned.m8n8.x2.shared.b16 {%0,%1}, [%2];"
                 : "=r"(r[0]), "=r"(r[1]) : "r"(a));
}
__device__ __forceinline__ void mma16816(float* c, const uint32_t* a, const uint32_t* b) {
    asm volatile(
        "mma.sync.aligned.m16n8k16.row.col.f32.f16.f16.f32 "
        "{%0,%1,%2,%3}, {%4,%5,%6,%7}, {%8,%9}, {%0,%1,%2,%3};"
        : "+f"(c[0]), "+f"(c[1]), "+f"(c[2]), "+f"(c[3])
        : "r"(a[0]), "r"(a[1]), "r"(a[2]), "r"(a[3]), "r"(b[0]), "r"(b[1]));
}
__device__ __forceinline__ void cpa16(uint32_t dst, const void* src) {
    asm volatile("cp.async.cg.shared.global [%0], [%1], 16;" :: "r"(dst), "l"(src));
}
#define CP_COMMIT() asm volatile("cp.async.commit_group;" ::: "memory")
#define CP_WAIT0()  asm volatile("cp.async.wait_group 0;" ::: "memory")
#define CP_WAIT1()  asm volatile("cp.async.wait_group 1;" ::: "memory")

__device__ __forceinline__ uint32_t pack2(float x0, float x1) {
    __half2 v = __floats2half2_rn(x0, x1);
    return *(uint32_t*)&v;
}
__device__ __forceinline__ float hfu(uint32_t u) {
    return __half2float(__ushort_as_half((unsigned short)(u & 0xffff)));
}
__device__ __forceinline__ uint32_t pack2lo(float x0, float h0, float x1, float h1) {
    __half2 v = __floats2half2_rn(x0 - h0, x1 - h1);
    return *(uint32_t*)&v;
}

// stage OW (dense 128x128 -> pitched) via cp.async (128 thr)
__device__ __forceinline__ void stage_tile(uint32_t dst, const uint4* src, int tid) {
#pragma unroll
    for (int i = tid; i < 2048; i += 128) {
        uint32_t d = ((uint32_t)(i >> 4) * PB) + ((i & 15) << 4);
        cpa16(dst + d, src + i);
    }
}
// stage W (pre-pitched 136xPB tile -> linear copy, 2312 uint4)
__device__ __forceinline__ void stage_w(uint32_t dst, const uint4* src, int tid) {
#pragma unroll
    for (int i = tid; i < 2312; i += 128) cpa16(dst + (uint32_t)i * 16, src + i);
}

// GEMM1: c[q][0..3] += A[rows R..R+15] @ W^T; cE += ei/ej cols (B rows 128/129)
__device__ __forceinline__ void gemm1(uint32_t aHi, uint32_t bW,
                                      float (&c)[16][4], float (&cE)[4],
                                      int R, int lid) {
    const int lm = lid >> 3, lr = lid & 7;
    const uint32_t aoff = (uint32_t)(R + lr + ((lm & 1) << 3)) * PB + ((lm >> 1) << 4);
    const uint32_t boff = (uint32_t)(lr + ((lm >> 1) << 3)) * PB + ((lm & 1) << 4);
    const uint32_t eoff = (uint32_t)(128 + (lid & 7)) * PB + (((lid >> 3) & 1) << 4);
#pragma unroll 2
    for (int k = 0; k < 8; k++) {
        uint32_t ah[4];
        ldsm4(ah, aHi + aoff + k * 32);
        uint32_t bE[2];
        ldsm2(bE, bW + eoff + k * 32);
        mma16816(cE, ah, bE);
#pragma unroll
        for (int jp = 0; jp < 8; jp++) {
            uint32_t bh[4];
            ldsm4(bh, bW + boff + (uint32_t)(jp * 16) * PB + k * 32);
            mma16816(c[2 * jp],     ah, bh);
            mma16816(c[2 * jp + 1], ah, bh + 2);
        }
    }
}

// ---------------- single setup kernel ----------------
__global__ void prep(const float* __restrict__ te, const float* __restrict__ W_in,
                     const float* __restrict__ b_in, const float* __restrict__ Wh,
                     const float* __restrict__ OW, const float* __restrict__ ah,
                     const float* __restrict__ om_i, const float* __restrict__ om_c,
                     const int* __restrict__ adj, const int* __restrict__ et,
                     float* __restrict__ out_tail) {
    int idx = blockIdx.x * 256 + threadIdx.x;   // grid 512 -> 131072 = 8*16384
    {
        int t = idx >> 14, rem = idx & 16383, row = rem >> 7, col = rem & 127;
        g_W[t * 18496 + row * 136 + col] = __float2half(Wh[idx]);
        int l = t >> 2, hh = t & 3;              // out_W[l][c=row][hh*128+g=col]
        g_OW[idx] = __float2half(OW[l * 65536 + row * 512 + hh * 128 + col]);
    }
    // wa rows (ei/ej fold): blocks 504..511 handle tile t = blockIdx.x - 504
    if (blockIdx.x >= 504) {
        int t = blockIdx.x - 504;
        int f = threadIdx.x;
        if (f < 128) {
            const float* wt = Wh + t * 16384;
            const float* av = ah + t * 256;
            float ss = 0.f, sd = 0.f;
#pragma unroll 4
            for (int g = 0; g < 128; g++) {
                float w = wt[g * 128 + f];
                ss += w * av[g];
                sd += w * av[128 + g];
            }
            __half* tw = g_W + t * 18496;
            tw[128 * 136 + f] = __float2half(ss);
            tw[129 * 136 + f] = __float2half(sd);
#pragma unroll
            for (int r = 130; r < 136; r++) tw[r * 136 + f] = __float2half(0.f);
        }
    }
    if (blockIdx.x == 0) {
        int t = threadIdx.x;
        if (t < 64) {
            float w = 0.f;
            if (adj[t]) { int e = et[t]; w = (e == 1) ? om_i[0] : ((e == 2) ? om_c[0] : 1.f); }
            out_tail[t] = w;
        }
        for (int i2 = t; i2 < 1024; i2 += 256) {
            int n = i2 >> 7, o = i2 & 127;
            const float* tr = te + n * 64;
            const float* wr = W_in + o * 64;
            float s = b_in[o];
#pragma unroll 8
            for (int d = 0; d < 64; d++) s += tr[d] * wr[d];
            g_htask[i2] = s;
        }
    }
}

// ---------------- main kernel ----------------
__global__ __launch_bounds__(128, 2)
void gat_tc(const float* __restrict__ se,
            const float* __restrict__ out_b, const float* __restrict__ ln_s,
            const float* __restrict__ ln_b, const int* __restrict__ adj,
            const int* __restrict__ et, const float* __restrict__ om_i,
            const float* __restrict__ om_c, float* __restrict__ out)
{
    extern __shared__ __align__(1024) unsigned char sm[];
    float* smf  = (float*)(sm + SM_SMALL);
    float* lnb  = smf;                // [2][384]: out_b | ln_scale | ln_bias
    float* ewf  = smf + 768;          // [64]
    int*   adji = (int*)(smf + 832);  // [64]

    const uint32_t smb = smem_u32(sm);
    const int tid = threadIdx.x;
    const int lid = tid & 31;
    const int wid = tid >> 5;                 // 0..3
    const int R     = wid << 4;               // warp's 16 rows
    const int group = lid >> 2;
    const int tg    = lid & 3;
    const long b0 = (long)blockIdx.x * 8;     // 8 batch elems per CTA

    // ---- prefetch head-0 W (group0) then OW (group1) ----
    stage_w(smb + SM_W, (const uint4*)g_W, tid);
    CP_COMMIT();
    stage_tile(smb + SM_OW, (const uint4*)g_OW, tid);
    CP_COMMIT();

    // ---- small constants ----
    if (tid < 64) {
        int e = et[tid];
        ewf[tid] = adj[tid] ? ((e == 1) ? om_i[0] : ((e == 2) ? om_c[0] : 1.f)) : 0.f;
        adji[tid] = adj[tid];
    }
#pragma unroll
    for (int l = 0; l < 2; l++) {
        lnb[l * 384 + tid]       = out_b[l * 128 + tid];
        lnb[l * 384 + 128 + tid] = ln_s[l * 128 + tid];
        lnb[l * 384 + 256 + tid] = ln_b[l * 128 + tid];
    }

    // ---- CTA phase-stagger: wave-1 second-slot CTAs delay ~6K cycles so the
    //      two co-resident CTAs per SM run anti-phase (GEMM vs scalar phases).
    //      Offset self-perpetuates across waves; cp.async continues behind it.
    if (blockIdx.x >= 148 && blockIdx.x < 296) {
        float x = (float)(tid + 1);
#pragma unroll 1
        for (int i = 0; i < 1536; i++) x = fmaf(x, 0.99993896f, 1e-7f);
        if (x == 123456.0f) ((volatile float*)smf)[900] = x;   // never true; keeps chain
    }

    // ---- build h tiles (hi used by GEMM1; lo only for residual): 64 rows ----
    {
        int r = tid & 63, f0 = (tid >> 6) * 64;
        const float* ser = se + (b0 + (r >> 3)) * 128;
        const float* htr = g_htask + (r & 7) * 128;
#pragma unroll 8
        for (int j = 0; j < 64; j += 2) {
            int f = f0 + j;
            float x0 = ser[f] + htr[f];
            float x1 = ser[f + 1] + htr[f + 1];
            uint32_t hiw = pack2(x0, x1);
            *(uint32_t*)(sm + SM_HHI + r * PB + f * 2) = hiw;
            *(uint32_t*)(sm + SM_HLO + r * PB + f * 2) =
                pack2lo(x0, hfu(hiw), x1, hfu(hiw >> 16));
        }
    }

    for (int l = 0; l < 2; l++) {
        float gacc[16][4];
#pragma unroll
        for (int i = 0; i < 16; i++)
#pragma unroll
            for (int j = 0; j < 4; j++) gacc[i][j] = 0.0f;

        for (int hh = 0; hh < 4; hh++) {
            const int t = l * 4 + hh;

            CP_WAIT1();          // W[t] landed (OW[t] may still be in flight)
            __syncthreads();

            // ---- GEMM1: cacc = h @ W^T ; cE = [ei0, ej0, ei1, ej1] fold ----
            float cacc[16][4], cE[4];
#pragma unroll
            for (int i = 0; i < 16; i++)
#pragma unroll
                for (int j = 0; j < 4; j++) cacc[i][j] = 0.0f;
            cE[0] = cE[1] = cE[2] = cE[3] = 0.0f;
            gemm1(smb + SM_HHI, smb + SM_W, cacc, cE, R, lid);

            __syncthreads();     // W[t] readers done -> safe to overwrite
            if (t < 7) {         // prefetch W[t+1]: overlaps softmax/hp/GEMM2
                stage_w(smb + SM_W, (const uint4*)(g_W + (size_t)(t + 1) * 18496), tid);
                CP_COMMIT();
            }

            // ---- pack Whh fragments to half2 (hp/GEMM2 fp16 quantization) ----
            uint32_t pc01[16], pc23[16];
#pragma unroll
            for (int q = 0; q < 16; q++) {
                pc01[q] = pack2(cacc[q][0], cacc[q][1]);
                pc23[q] = pack2(cacc[q][2], cacc[q][3]);
            }

            // ---- warp-local softmax; ei/ej live in cE at tg=0 lanes ----
            float att0[8], att1[8];
            {
                float ei0 = __shfl_sync(0xffffffffu, cE[0], group * 4);
                float ei1 = __shfl_sync(0xffffffffu, cE[2], group * 4);
                float mx0 = -1e30f, mx1 = -1e30f;
#pragma unroll
                for (int m = 0; m < 8; m++) {
                    float ejm0 = __shfl_sync(0xffffffffu, cE[1], m * 4);
                    float ejm1 = __shfl_sync(0xffffffffu, cE[3], m * 4);
                    float w = ewf[group * 8 + m];
                    int   ad = adji[group * 8 + m];
                    float v0 = 0.f, v1 = 0.f;
                    if (ad) {
                        float x0 = ei0 + ejm0; v0 = (x0 > 0.f ? x0 : 0.2f * x0) * w;
                        float x1 = ei1 + ejm1; v1 = (x1 > 0.f ? x1 : 0.2f * x1) * w;
                    }
                    att0[m] = v0; att1[m] = v1;
                    mx0 = fmaxf(mx0, v0); mx1 = fmaxf(mx1, v1);
                }
                float s0 = 0.f, s1 = 0.f;
#pragma unroll
                for (int m = 0; m < 8; m++) {
                    att0[m] = __expf(att0[m] - mx0); s0 += att0[m];
                    att1[m] = __expf(att1[m] - mx1); s1 += att1[m];
                }
                float i0 = 1.f / s0, i1 = 1.f / s1;
#pragma unroll
                for (int m = 0; m < 8; m++) { att0[m] *= i0; att1[m] *= i1; }
            }

            // ---- hp = elu(att @ Whh) as 16 MMAs: batches stacked along k ----
            uint32_t afHi[8][4];
            {
                uint32_t a_frag[4];
                a_frag[0] = pack2(att0[2 * tg], att0[2 * tg + 1]);   // r=g,   k lo
                a_frag[1] = 0u;
                a_frag[2] = 0u;
                a_frag[3] = pack2(att1[2 * tg], att1[2 * tg + 1]);   // r=g+8, k hi
                const uint32_t sel = (group & 1) ? 0x7632u : 0x5410u;
                const int src0 = (2 * tg) * 4 + (group >> 1);
                const int src1 = src0 + 4;
#pragma unroll
                for (int q = 0; q < 16; q++) {
                    uint32_t w0 = __shfl_sync(0xffffffffu, pc01[q], src0);
                    uint32_t w1 = __shfl_sync(0xffffffffu, pc01[q], src1);
                    uint32_t v0 = __shfl_sync(0xffffffffu, pc23[q], src0);
                    uint32_t v1 = __shfl_sync(0xffffffffu, pc23[q], src1);
                    uint32_t b_frag[2];
                    b_frag[0] = __byte_perm(w0, w1, sel);   // batch0 rows 2tg,2tg+1
                    b_frag[1] = __byte_perm(v0, v1, sel);   // batch1 rows 2tg,2tg+1
                    float c4[4] = {0.f, 0.f, 0.f, 0.f};
                    mma16816(c4, a_frag, b_frag);
                    float h0a = c4[0], h0b = c4[1], h1a = c4[2], h1b = c4[3];
                    h0a = h0a > 0.f ? h0a : (__expf(h0a) - 1.f);
                    h0b = h0b > 0.f ? h0b : (__expf(h0b) - 1.f);
                    h1a = h1a > 0.f ? h1a : (__expf(h1a) - 1.f);
                    h1b = h1b > 0.f ? h1b : (__expf(h1b) - 1.f);
                    int kk = q >> 1, pos = (q & 1) << 1;
                    afHi[kk][pos]     = pack2(h0a, h0b);
                    afHi[kk][pos + 1] = pack2(h1a, h1b);
                }
            }

            if (t < 7) CP_WAIT1(); else CP_WAIT0();   // OW[t] landed
            __syncthreads();

            // ---- GEMM2: gacc += hp @ outW^T (single product, A regs) ----
            {
                const int lm = lid >> 3, lr = lid & 7;
                const uint32_t boff = (uint32_t)(lr + ((lm >> 1) << 3)) * PB + ((lm & 1) << 4);
                const uint32_t bS = smb + SM_OW;
#pragma unroll
                for (int kk = 0; kk < 8; kk++) {
#pragma unroll
                    for (int jp = 0; jp < 8; jp++) {
                        uint32_t bh[4];
                        ldsm4(bh, bS + boff + (uint32_t)(jp * 16) * PB + kk * 32);
                        mma16816(gacc[2 * jp],     afHi[kk], bh);
                        mma16816(gacc[2 * jp + 1], afHi[kk], bh + 2);
                    }
                }
            }

            __syncthreads();     // OW[t] readers done -> safe to overwrite
            if (t < 7) {         // prefetch OW[t+1]: overlaps next head's GEMM1..hp
                stage_tile(smb + SM_OW, (const uint4*)(g_OW + ((t + 1) << 14)), tid);
                CP_COMMIT();
            }
        } // heads

        // ---- residual + bias + LayerNorm (warp-local rows; h = hi+lo) ----
        {
            const float* lb = lnb + l * 384;
            int r0 = R + group, r1 = r0 + 8;
            float s0 = 0.f, q0 = 0.f, s1 = 0.f, q1 = 0.f;
            float x0v[16][2], x1v[16][2];
#pragma unroll
            for (int jp = 0; jp < 16; jp++) {
                int col = jp * 8 + tg * 2;
                uint32_t h0h = *(uint32_t*)(sm + SM_HHI + r0 * PB + col * 2);
                uint32_t h0l = *(uint32_t*)(sm + SM_HLO + r0 * PB + col * 2);
                uint32_t h1h = *(uint32_t*)(sm + SM_HHI + r1 * PB + col * 2);
                uint32_t h1l = *(uint32_t*)(sm + SM_HLO + r1 * PB + col * 2);
                float x00 = gacc[jp][0] + hfu(h0h) + hfu(h0l) + lb[col];
                float x01 = gacc[jp][1] + hfu(h0h >> 16) + hfu(h0l >> 16) + lb[col + 1];
                float x10 = gacc[jp][2] + hfu(h1h) + hfu(h1l) + lb[col];
                float x11 = gacc[jp][3] + hfu(h1h >> 16) + hfu(h1l >> 16) + lb[col + 1];
                x0v[jp][0] = x00; x0v[jp][1] = x01;
                x1v[jp][0] = x10; x1v[jp][1] = x11;
                s0 += x00 + x01; q0 += x00 * x00 + x01 * x01;
                s1 += x10 + x11; q1 += x10 * x10 + x11 * x11;
            }
#pragma unroll
            for (int o = 1; o < 4; o <<= 1) {
                s0 += __shfl_xor_sync(0xffffffffu, s0, o);
                q0 += __shfl_xor_sync(0xffffffffu, q0, o);
                s1 += __shfl_xor_sync(0xffffffffu, s1, o);
                q1 += __shfl_xor_sync(0xffffffffu, q1, o);
            }
            float mu0 = s0 * 0.0078125f, mu1 = s1 * 0.0078125f;
            float rstd0 = rsqrtf(q0 * 0.0078125f - mu0 * mu0 + 1e-5f);
            float rstd1 = rsqrtf(q1 * 0.0078125f - mu1 * mu1 + 1e-5f);
#pragma unroll
            for (int jp = 0; jp < 16; jp++) {
                int col = jp * 8 + tg * 2;
                float y00 = (x0v[jp][0] - mu0) * rstd0 * lb[128 + col]     + lb[256 + col];
                float y01 = (x0v[jp][1] - mu0) * rstd0 * lb[128 + col + 1] + lb[256 + col + 1];
                float y10 = (x1v[jp][0] - mu1) * rstd1 * lb[128 + col]     + lb[256 + col];
                float y11 = (x1v[jp][1] - mu1) * rstd1 * lb[128 + col + 1] + lb[256 + col + 1];
                if (l == 0) {
                    uint32_t w0 = pack2(y00, y01), w1 = pack2(y10, y11);
                    *(uint32_t*)(sm + SM_HHI + r0 * PB + col * 2) = w0;
                    *(uint32_t*)(sm + SM_HLO + r0 * PB + col * 2) =
                        pack2lo(y00, hfu(w0), y01, hfu(w0 >> 16));
                    *(uint32_t*)(sm + SM_HHI + r1 * PB + col * 2) = w1;
                    *(uint32_t*)(sm + SM_HLO + r1 * PB + col * 2) =
                        pack2lo(y10, hfu(w1), y11, hfu(w1 >> 16));
                } else {
                    *(float2*)(out + ((long)blockIdx.x * 64 + r0) * 128 + col) =
                        make_float2(y00, y01);
                    *(float2*)(out + ((long)blockIdx.x * 64 + r1) * 128 + col) =
                        make_float2(y10, y11);
                }
            }
            __syncwarp();   // h-tile writes visible to next-layer GEMM1 (warp-local)
        }
    } // layers
}

// ---------------------------------------------------------------------------
extern "C" void kernel_launch(void* const* d_in, const int* in_sizes, int n_in,
                              void* d_out, int out_size)
{
    const float* se      = (const float*)d_in[0];
    const float* te      = (const float*)d_in[1];
    const float* W_in    = (const float*)d_in[2];
    const float* b_in    = (const float*)d_in[3];
    const float* W_heads = (const float*)d_in[4];
    const float* a_heads = (const float*)d_in[5];
    const float* out_W   = (const float*)d_in[6];
    const float* out_b   = (const float*)d_in[7];
    const float* ln_s    = (const float*)d_in[8];
    const float* ln_b    = (const float*)d_in[9];
    const float* om_i    = (const float*)d_in[10];
    const float* om_c    = (const float*)d_in[11];
    const int*   adj     = (const int*)d_in[12];
    const int*   et      = (const int*)d_in[13];
    float* out = (float*)d_out;

    int B = in_sizes[0] / 128;
    size_t tail = (size_t)B * 8 * 128;

    prep<<<512, 256>>>(te, W_in, b_in, W_heads, out_W, a_heads,
                       om_i, om_c, adj, et, out + tail);

    cudaFuncSetAttribute(gat_tc, cudaFuncAttributeMaxDynamicSharedMemorySize, SMEM_BYTES);
    gat_tc<<<B / 8, 128, SMEM_BYTES>>>(se, out_b, ln_s, ln_b,
                                       adj, et, om_i, om_c, out);
}

// round 17
// speedup vs baseline: 1.1566x; 1.1566x over previous
#include <cuda_runtime.h>
#include <cuda_fp16.h>
#include <cstdint>
#include <math.h>

// ===========================================================================
// TaskGraphGAT — round 16: R14 best (424us) + software-pipelined LDSM in both
// GEMMs (volatile asm was forcing load->use distance 0; with 2 warps/SMSP the
// LDS latency was exposed every iteration), no-max softmax, stagger removed.
// ===========================================================================

#define PB 272          // fp16 tile pitch in BYTES (136 halves)

// ---------------- SMEM map (bytes) ----------------
#define SM_HHI   0          // h hi (64 x 136 fp16 = 17408 B) -> GEMM1 A
#define SM_HLO   17408      // h lo (residual accuracy only)
#define SM_W     34816      // W tile fp16, 136 rows x PB = 36992 B (rows 128/129 = wa)
#define SM_OW    71808      // outW tile fp16, 128 rows x PB = 34816 B
#define SM_SMALL 106624     // lnb[768] | ewf[64] | adji[64]
#define SMEM_BYTES 110208

// ---------------- device globals (written by prep) ----------------
__device__ float g_htask[8 * 128];
__device__ __align__(16) __half g_W[8 * 18496];    // pre-pitched 136x136 tiles
__device__ __align__(16) __half g_OW[8 * 16384];   // out_W rearranged fp16

// ---------------- helpers ----------------
__device__ __forceinline__ uint32_t smem_u32(const void* p) {
    uint32_t a;
    asm("{ .reg .u64 t; cvta.to.shared.u64 t, %1; cvt.u32.u64 %0, t; }" : "=r"(a) : "l"(p));
    return a;
}
__device__ __forceinline__ void ldsm4(uint32_t* r, uint32_t a) {
    asm volatile("ldmatrix.sync.aligned.m8n8.x4.shared.b16 {%0,%1,%2,%3}, [%4];"
                 : "=r"(r[0]), "=r"(r[1]), "=r"(r[2]), "=r"(r[3]) : "r"(a));
}
__device__ __forceinline__ void ldsm2(uint32_t* r, uint32_t a) {
    asm volatile("ldmatrix.sync.aligned.m8n8.x2.shared.b16 {%0,%1}, [%2];"
                 : "=r"(r[0]), "=r"(r[1]) : "r"(a));
}
__device__ __forceinline__ void mma16816(float* c, const uint32_t* a, const uint32_t* b) {
    asm volatile(
        "mma.sync.aligned.m16n8k16.row.col.f32.f16.f16.f32 "
        "{%0,%1,%2,%3}, {%4,%5,%6,%7}, {%8,%9}, {%0,%1,%2,%3};"
        : "+f"(c[0]), "+f"(c[1]), "+f"(c[2]), "+f"(c[3])
        : "r"(a[0]), "r"(a[1]), "r"(a[2]), "r"(a[3]), "r"(b[0]), "r"(b[1]));
}
__device__ __forceinline__ void cpa16(uint32_t dst, const void* src) {
    asm volatile("cp.async.cg.shared.global [%0], [%1], 16;" :: "r"(dst), "l"(src));
}
#define CP_COMMIT() asm volatile("cp.async.commit_group;" ::: "memory")
#define CP_WAIT0()  asm volatile("cp.async.wait_group 0;" ::: "memory")
#define CP_WAIT1()  asm volatile("cp.async.wait_group 1;" ::: "memory")

__device__ __forceinline__ uint32_t pack2(float x0, float x1) {
    __half2 v = __floats2half2_rn(x0, x1);
    return *(uint32_t*)&v;
}
__device__ __forceinline__ float hfu(uint32_t u) {
    return __half2float(__ushort_as_half((unsigned short)(u & 0xffff)));
}
__device__ __forceinline__ uint32_t pack2lo(float x0, float h0, float x1, float h1) {
    __half2 v = __floats2half2_rn(x0 - h0, x1 - h1);
    return *(uint32_t*)&v;
}

// stage OW (dense 128x128 -> pitched) via cp.async (128 thr)
__device__ __forceinline__ void stage_tile(uint32_t dst, const uint4* src, int tid) {
#pragma unroll
    for (int i = tid; i < 2048; i += 128) {
        uint32_t d = ((uint32_t)(i >> 4) * PB) + ((i & 15) << 4);
        cpa16(dst + d, src + i);
    }
}
// stage W (pre-pitched 136xPB tile -> linear copy, 2312 uint4)
__device__ __forceinline__ void stage_w(uint32_t dst, const uint4* src, int tid) {
#pragma unroll
    for (int i = tid; i < 2312; i += 128) cpa16(dst + (uint32_t)i * 16, src + i);
}

// GEMM1 (software-pipelined): c += A @ W^T ; cE += ei/ej cols (B rows 128/129)
__device__ __forceinline__ void gemm1(uint32_t aHi, uint32_t bW,
                                      float (&c)[16][4], float (&cE)[4],
                                      int R, int lid) {
    const int lm = lid >> 3, lr = lid & 7;
    const uint32_t aoff = (uint32_t)(R + lr + ((lm & 1) << 3)) * PB + ((lm >> 1) << 4);
    const uint32_t boff = (uint32_t)(lr + ((lm >> 1) << 3)) * PB + ((lm & 1) << 4);
    const uint32_t eoff = (uint32_t)(128 + (lid & 7)) * PB + (((lid >> 3) & 1) << 4);

    uint32_t ah[2][4], bE[2][2], bh[2][4];
    ldsm4(ah[0], aHi + aoff);
    ldsm2(bE[0], bW + eoff);
    ldsm4(bh[0], bW + boff);
#pragma unroll
    for (int k = 0; k < 8; k++) {
        const int cur = k & 1, nxt = cur ^ 1;
        if (k < 7) {
            ldsm4(ah[nxt], aHi + aoff + (k + 1) * 32);
            ldsm2(bE[nxt], bW + eoff + (k + 1) * 32);
        }
#pragma unroll
        for (int jp = 0; jp < 8; jp++) {
            const int cb = jp & 1, nb = cb ^ 1;
            if (jp < 7) {
                ldsm4(bh[nb], bW + boff + (uint32_t)((jp + 1) * 16) * PB + k * 32);
            } else if (k < 7) {
                ldsm4(bh[nb], bW + boff + (k + 1) * 32);
            }
            mma16816(c[2 * jp],     ah[cur], bh[cb]);
            mma16816(c[2 * jp + 1], ah[cur], bh[cb] + 2);
        }
        mma16816(cE, ah[cur], bE[cur]);
    }
}

// ---------------- single setup kernel ----------------
__global__ void prep(const float* __restrict__ te, const float* __restrict__ W_in,
                     const float* __restrict__ b_in, const float* __restrict__ Wh,
                     const float* __restrict__ OW, const float* __restrict__ ah,
                     const float* __restrict__ om_i, const float* __restrict__ om_c,
                     const int* __restrict__ adj, const int* __restrict__ et,
                     float* __restrict__ out_tail) {
    int idx = blockIdx.x * 256 + threadIdx.x;   // grid 512 -> 131072 = 8*16384
    {
        int t = idx >> 14, rem = idx & 16383, row = rem >> 7, col = rem & 127;
        g_W[t * 18496 + row * 136 + col] = __float2half(Wh[idx]);
        int l = t >> 2, hh = t & 3;              // out_W[l][c=row][hh*128+g=col]
        g_OW[idx] = __float2half(OW[l * 65536 + row * 512 + hh * 128 + col]);
    }
    // wa rows (ei/ej fold): blocks 504..511 handle tile t = blockIdx.x - 504
    if (blockIdx.x >= 504) {
        int t = blockIdx.x - 504;
        int f = threadIdx.x;
        if (f < 128) {
            const float* wt = Wh + t * 16384;
            const float* av = ah + t * 256;
            float ss = 0.f, sd = 0.f;
#pragma unroll 4
            for (int g = 0; g < 128; g++) {
                float w = wt[g * 128 + f];
                ss += w * av[g];
                sd += w * av[128 + g];
            }
            __half* tw = g_W + t * 18496;
            tw[128 * 136 + f] = __float2half(ss);
            tw[129 * 136 + f] = __float2half(sd);
#pragma unroll
            for (int r = 130; r < 136; r++) tw[r * 136 + f] = __float2half(0.f);
        }
    }
    if (blockIdx.x == 0) {
        int t = threadIdx.x;
        if (t < 64) {
            float w = 0.f;
            if (adj[t]) { int e = et[t]; w = (e == 1) ? om_i[0] : ((e == 2) ? om_c[0] : 1.f); }
            out_tail[t] = w;
        }
        for (int i2 = t; i2 < 1024; i2 += 256) {
            int n = i2 >> 7, o = i2 & 127;
            const float* tr = te + n * 64;
            const float* wr = W_in + o * 64;
            float s = b_in[o];
#pragma unroll 8
            for (int d = 0; d < 64; d++) s += tr[d] * wr[d];
            g_htask[i2] = s;
        }
    }
}

// ---------------- main kernel ----------------
__global__ __launch_bounds__(128, 2)
void gat_tc(const float* __restrict__ se,
            const float* __restrict__ out_b, const float* __restrict__ ln_s,
            const float* __restrict__ ln_b, const int* __restrict__ adj,
            const int* __restrict__ et, const float* __restrict__ om_i,
            const float* __restrict__ om_c, float* __restrict__ out)
{
    extern __shared__ __align__(1024) unsigned char sm[];
    float* smf  = (float*)(sm + SM_SMALL);
    float* lnb  = smf;                // [2][384]: out_b | ln_scale | ln_bias
    float* ewf  = smf + 768;          // [64]
    int*   adji = (int*)(smf + 832);  // [64]

    const uint32_t smb = smem_u32(sm);
    const int tid = threadIdx.x;
    const int lid = tid & 31;
    const int wid = tid >> 5;                 // 0..3
    const int R     = wid << 4;               // warp's 16 rows
    const int group = lid >> 2;
    const int tg    = lid & 3;
    const long b0 = (long)blockIdx.x * 8;     // 8 batch elems per CTA

    // ---- prefetch head-0 W (group0) then OW (group1) ----
    stage_w(smb + SM_W, (const uint4*)g_W, tid);
    CP_COMMIT();
    stage_tile(smb + SM_OW, (const uint4*)g_OW, tid);
    CP_COMMIT();

    // ---- small constants ----
    if (tid < 64) {
        int e = et[tid];
        ewf[tid] = adj[tid] ? ((e == 1) ? om_i[0] : ((e == 2) ? om_c[0] : 1.f)) : 0.f;
        adji[tid] = adj[tid];
    }
#pragma unroll
    for (int l = 0; l < 2; l++) {
        lnb[l * 384 + tid]       = out_b[l * 128 + tid];
        lnb[l * 384 + 128 + tid] = ln_s[l * 128 + tid];
        lnb[l * 384 + 256 + tid] = ln_b[l * 128 + tid];
    }

    // ---- build h tiles (hi used by GEMM1; lo only for residual): 64 rows ----
    {
        int r = tid & 63, f0 = (tid >> 6) * 64;
        const float* ser = se + (b0 + (r >> 3)) * 128;
        const float* htr = g_htask + (r & 7) * 128;
#pragma unroll 8
        for (int j = 0; j < 64; j += 2) {
            int f = f0 + j;
            float x0 = ser[f] + htr[f];
            float x1 = ser[f + 1] + htr[f + 1];
            uint32_t hiw = pack2(x0, x1);
            *(uint32_t*)(sm + SM_HHI + r * PB + f * 2) = hiw;
            *(uint32_t*)(sm + SM_HLO + r * PB + f * 2) =
                pack2lo(x0, hfu(hiw), x1, hfu(hiw >> 16));
        }
    }

    for (int l = 0; l < 2; l++) {
        float gacc[16][4];
#pragma unroll
        for (int i = 0; i < 16; i++)
#pragma unroll
            for (int j = 0; j < 4; j++) gacc[i][j] = 0.0f;

        for (int hh = 0; hh < 4; hh++) {
            const int t = l * 4 + hh;

            CP_WAIT1();          // W[t] landed (OW[t] may still be in flight)
            __syncthreads();

            // ---- GEMM1: cacc = h @ W^T ; cE = [ei0, ej0, ei1, ej1] fold ----
            float cacc[16][4], cE[4];
#pragma unroll
            for (int i = 0; i < 16; i++)
#pragma unroll
                for (int j = 0; j < 4; j++) cacc[i][j] = 0.0f;
            cE[0] = cE[1] = cE[2] = cE[3] = 0.0f;
            gemm1(smb + SM_HHI, smb + SM_W, cacc, cE, R, lid);

            __syncthreads();     // W[t] readers done -> safe to overwrite
            if (t < 7) {         // prefetch W[t+1]: overlaps softmax/hp/GEMM2
                stage_w(smb + SM_W, (const uint4*)(g_W + (size_t)(t + 1) * 18496), tid);
                CP_COMMIT();
            }

            // ---- pack Whh fragments to half2 (hp/GEMM2 fp16 quantization) ----
            uint32_t pc01[16], pc23[16];
#pragma unroll
            for (int q = 0; q < 16; q++) {
                pc01[q] = pack2(cacc[q][0], cacc[q][1]);
                pc23[q] = pack2(cacc[q][2], cacc[q][3]);
            }

            // ---- warp-local softmax (no max-sub; |logits| < ~3 by construction) ----
            float att0[8], att1[8];
            {
                float ei0 = __shfl_sync(0xffffffffu, cE[0], group * 4);
                float ei1 = __shfl_sync(0xffffffffu, cE[2], group * 4);
                float s0 = 0.f, s1 = 0.f;
#pragma unroll
                for (int m = 0; m < 8; m++) {
                    float ejm0 = __shfl_sync(0xffffffffu, cE[1], m * 4);
                    float ejm1 = __shfl_sync(0xffffffffu, cE[3], m * 4);
                    float w = ewf[group * 8 + m];
                    int   ad = adji[group * 8 + m];
                    float v0 = 0.f, v1 = 0.f;
                    if (ad) {
                        float x0 = ei0 + ejm0; v0 = (x0 > 0.f ? x0 : 0.2f * x0) * w;
                        float x1 = ei1 + ejm1; v1 = (x1 > 0.f ? x1 : 0.2f * x1) * w;
                    }
                    att0[m] = __expf(v0); s0 += att0[m];
                    att1[m] = __expf(v1); s1 += att1[m];
                }
                float i0 = 1.f / s0, i1 = 1.f / s1;
#pragma unroll
                for (int m = 0; m < 8; m++) { att0[m] *= i0; att1[m] *= i1; }
            }

            // ---- hp = elu(att @ Whh) as 16 MMAs: batches stacked along k ----
            uint32_t afHi[8][4];
            {
                uint32_t a_frag[4];
                a_frag[0] = pack2(att0[2 * tg], att0[2 * tg + 1]);   // r=g,   k lo
                a_frag[1] = 0u;
                a_frag[2] = 0u;
                a_frag[3] = pack2(att1[2 * tg], att1[2 * tg + 1]);   // r=g+8, k hi
                const uint32_t sel = (group & 1) ? 0x7632u : 0x5410u;
                const int src0 = (2 * tg) * 4 + (group >> 1);
                const int src1 = src0 + 4;
#pragma unroll
                for (int q = 0; q < 16; q++) {
                    uint32_t w0 = __shfl_sync(0xffffffffu, pc01[q], src0);
                    uint32_t w1 = __shfl_sync(0xffffffffu, pc01[q], src1);
                    uint32_t v0 = __shfl_sync(0xffffffffu, pc23[q], src0);
                    uint32_t v1 = __shfl_sync(0xffffffffu, pc23[q], src1);
                    uint32_t b_frag[2];
                    b_frag[0] = __byte_perm(w0, w1, sel);   // batch0 rows 2tg,2tg+1
                    b_frag[1] = __byte_perm(v0, v1, sel);   // batch1 rows 2tg,2tg+1
                    float c4[4] = {0.f, 0.f, 0.f, 0.f};
                    mma16816(c4, a_frag, b_frag);
                    float h0a = c4[0], h0b = c4[1], h1a = c4[2], h1b = c4[3];
                    h0a = h0a > 0.f ? h0a : (__expf(h0a) - 1.f);
                    h0b = h0b > 0.f ? h0b : (__expf(h0b) - 1.f);
                    h1a = h1a > 0.f ? h1a : (__expf(h1a) - 1.f);
                    h1b = h1b > 0.f ? h1b : (__expf(h1b) - 1.f);
                    int kk = q >> 1, pos = (q & 1) << 1;
                    afHi[kk][pos]     = pack2(h0a, h0b);
                    afHi[kk][pos + 1] = pack2(h1a, h1b);
                }
            }

            if (t < 7) CP_WAIT1(); else CP_WAIT0();   // OW[t] landed
            __syncthreads();

            // ---- GEMM2 (software-pipelined): gacc += hp @ outW^T ----
            {
                const int lm = lid >> 3, lr = lid & 7;
                const uint32_t boff = (uint32_t)(lr + ((lm >> 1) << 3)) * PB + ((lm & 1) << 4);
                const uint32_t bS = smb + SM_OW;
                uint32_t bh[2][4];
                ldsm4(bh[0], bS + boff);
#pragma unroll
                for (int kk = 0; kk < 8; kk++) {
#pragma unroll
                    for (int jp = 0; jp < 8; jp++) {
                        const int i = kk * 8 + jp;
                        const int cb = i & 1, nb = cb ^ 1;
                        if (i < 63) {
                            const int jn = (jp + 1) & 7;
                            const int kn = kk + (jp == 7);
                            ldsm4(bh[nb], bS + boff + (uint32_t)(jn * 16) * PB + kn * 32);
                        }
                        mma16816(gacc[2 * jp],     afHi[kk], bh[cb]);
                        mma16816(gacc[2 * jp + 1], afHi[kk], bh[cb] + 2);
                    }
                }
            }

            __syncthreads();     // OW[t] readers done -> safe to overwrite
            if (t < 7) {         // prefetch OW[t+1]: overlaps next head's GEMM1..hp
                stage_tile(smb + SM_OW, (const uint4*)(g_OW + ((t + 1) << 14)), tid);
                CP_COMMIT();
            }
        } // heads

        // ---- residual + bias + LayerNorm (warp-local rows; h = hi+lo) ----
        {
            const float* lb = lnb + l * 384;
            int r0 = R + group, r1 = r0 + 8;
            float s0 = 0.f, q0 = 0.f, s1 = 0.f, q1 = 0.f;
            float x0v[16][2], x1v[16][2];
#pragma unroll
            for (int jp = 0; jp < 16; jp++) {
                int col = jp * 8 + tg * 2;
                uint32_t h0h = *(uint32_t*)(sm + SM_HHI + r0 * PB + col * 2);
                uint32_t h0l = *(uint32_t*)(sm + SM_HLO + r0 * PB + col * 2);
                uint32_t h1h = *(uint32_t*)(sm + SM_HHI + r1 * PB + col * 2);
                uint32_t h1l = *(uint32_t*)(sm + SM_HLO + r1 * PB + col * 2);
                float x00 = gacc[jp][0] + hfu(h0h) + hfu(h0l) + lb[col];
                float x01 = gacc[jp][1] + hfu(h0h >> 16) + hfu(h0l >> 16) + lb[col + 1];
                float x10 = gacc[jp][2] + hfu(h1h) + hfu(h1l) + lb[col];
                float x11 = gacc[jp][3] + hfu(h1h >> 16) + hfu(h1l >> 16) + lb[col + 1];
                x0v[jp][0] = x00; x0v[jp][1] = x01;
                x1v[jp][0] = x10; x1v[jp][1] = x11;
                s0 += x00 + x01; q0 += x00 * x00 + x01 * x01;
                s1 += x10 + x11; q1 += x10 * x10 + x11 * x11;
            }
#pragma unroll
            for (int o = 1; o < 4; o <<= 1) {
                s0 += __shfl_xor_sync(0xffffffffu, s0, o);
                q0 += __shfl_xor_sync(0xffffffffu, q0, o);
                s1 += __shfl_xor_sync(0xffffffffu, s1, o);
                q1 += __shfl_xor_sync(0xffffffffu, q1, o);
            }
            float mu0 = s0 * 0.0078125f, mu1 = s1 * 0.0078125f;
            float rstd0 = rsqrtf(q0 * 0.0078125f - mu0 * mu0 + 1e-5f);
            float rstd1 = rsqrtf(q1 * 0.0078125f - mu1 * mu1 + 1e-5f);
#pragma unroll
            for (int jp = 0; jp < 16; jp++) {
                int col = jp * 8 + tg * 2;
                float y00 = (x0v[jp][0] - mu0) * rstd0 * lb[128 + col]     + lb[256 + col];
                float y01 = (x0v[jp][1] - mu0) * rstd0 * lb[128 + col + 1] + lb[256 + col + 1];
                float y10 = (x1v[jp][0] - mu1) * rstd1 * lb[128 + col]     + lb[256 + col];
                float y11 = (x1v[jp][1] - mu1) * rstd1 * lb[128 + col + 1] + lb[256 + col + 1];
                if (l == 0) {
                    uint32_t w0 = pack2(y00, y01), w1 = pack2(y10, y11);
                    *(uint32_t*)(sm + SM_HHI + r0 * PB + col * 2) = w0;
                    *(uint32_t*)(sm + SM_HLO + r0 * PB + col * 2) =
                        pack2lo(y00, hfu(w0), y01, hfu(w0 >> 16));
                    *(uint32_t*)(sm + SM_HHI + r1 * PB + col * 2) = w1;
                    *(uint32_t*)(sm + SM_HLO + r1 * PB + col * 2) =
                        pack2lo(y10, hfu(w1), y11, hfu(w1 >> 16));
                } else {
                    *(float2*)(out + ((long)blockIdx.x * 64 + r0) * 128 + col) =
                        make_float2(y00, y01);
                    *(float2*)(out + ((long)blockIdx.x * 64 + r1) * 128 + col) =
                        make_float2(y10, y11);
                }
            }
            __syncwarp();   // h-tile writes visible to next-layer GEMM1 (warp-local)
        }
    } // layers
}

// ---------------------------------------------------------------------------
extern "C" void kernel_launch(void* const* d_in, const int* in_sizes, int n_in,
                              void* d_out, int out_size)
{
    const float* se      = (const float*)d_in[0];
    const float* te      = (const float*)d_in[1];
    const float* W_in    = (const float*)d_in[2];
    const float* b_in    = (const float*)d_in[3];
    const float* W_heads = (const float*)d_in[4];
    const float* a_heads = (const float*)d_in[5];
    const float* out_W   = (const float*)d_in[6];
    const float* out_b   = (const float*)d_in[7];
    const float* ln_s    = (const float*)d_in[8];
    const float* ln_b    = (const float*)d_in[9];
    const float* om_i    = (const float*)d_in[10];
    const float* om_c    = (const float*)d_in[11];
    const int*   adj     = (const int*)d_in[12];
    const int*   et      = (const int*)d_in[13];
    float* out = (float*)d_out;

    int B = in_sizes[0] / 128;
    size_t tail = (size_t)B * 8 * 128;

    prep<<<512, 256>>>(te, W_in, b_in, W_heads, out_W, a_heads,
                       om_i, om_c, adj, et, out + tail);

    cudaFuncSetAttribute(gat_tc, cudaFuncAttributeMaxDynamicSharedMemorySize, SMEM_BYTES);
    gat_tc<<<B / 8, 128, SMEM_BYTES>>>(se, out_b, ln_s, ln_b,
                                       adj, et, om_i, om_c, out);
}